// round 3
// baseline (speedup 1.0000x reference)
#include <cuda_runtime.h>
#include <math.h>

// Problem constants
#define BATCH 4
#define NSEQ  2048
#define DIMX  512
#define HEADS 8
#define DHEAD 64
#define M_ROWS (BATCH * NSEQ)      // 8192
#define N_QKV  (3 * DIMX)          // 1536
#define ATT_SCALE 0.125f           // 64^-0.5

// Scratch (device globals; no runtime allocation allowed)
__device__ float g_Q[BATCH * HEADS * NSEQ * DHEAD];  // [bh][n][64], pre-scaled
__device__ float g_K[BATCH * HEADS * NSEQ * DHEAD];
__device__ float g_V[BATCH * HEADS * NSEQ * DHEAD];
__device__ float g_O[M_ROWS * DIMX];                 // [b*n][h*64+dh]

// ---------------------------------------------------------------------------
// Packed f32x2 helpers (B300 FFMA2 path: 2x fp32 throughput, only via PTX)
// ---------------------------------------------------------------------------
__device__ __forceinline__ double ffma2(double a, double b, double c) {
    double d;
    asm("fma.rn.f32x2 %0, %1, %2, %3;" : "=d"(d) : "d"(a), "d"(b), "d"(c));
    return d;
}
__device__ __forceinline__ double fmul2(double a, double b) {
    double d;
    asm("mul.rn.f32x2 %0, %1, %2;" : "=d"(d) : "d"(a), "d"(b));
    return d;
}
__device__ __forceinline__ double fpack2(float lo, float hi) {
    double d;
    asm("mov.b64 %0, {%1, %2};" : "=d"(d) : "f"(lo), "f"(hi));
    return d;
}
__device__ __forceinline__ void funpack2(double d, float& lo, float& hi) {
    asm("mov.b64 {%0, %1}, %2;" : "=f"(lo), "=f"(hi) : "d"(d));
}

// ---------------------------------------------------------------------------
// Kernel 1: QKV GEMM  (A = x [8192,512], B = w_qkv [512,1536])
// 128x128 tile, BK=8, 256 threads, 8x8 per thread, FFMA2 packed over N.
// ---------------------------------------------------------------------------
__global__ __launch_bounds__(256) void qkv_gemm_kernel(
    const float* __restrict__ A, const float* __restrict__ B)
{
    __shared__ float As[8][128];
    __shared__ float Bs[8][128];

    const int tid = threadIdx.x;
    const int m0 = blockIdx.y * 128;
    const int n0 = blockIdx.x * 128;
    const int tx = tid & 15;
    const int ty = tid >> 4;

    const int a_row = tid >> 1;          // 0..127
    const int a_col = (tid & 1) * 4;     // 0 or 4
    const int b_row = tid >> 5;          // 0..7
    const int b_col = (tid & 31) * 4;    // 0..124

    double acc2[8][4];                   // packed pairs over j
#pragma unroll
    for (int i = 0; i < 8; i++)
#pragma unroll
        for (int j = 0; j < 4; j++) acc2[i][j] = 0.0;

    for (int k0 = 0; k0 < DIMX; k0 += 8) {
        float4 av = *(const float4*)&A[(size_t)(m0 + a_row) * DIMX + k0 + a_col];
        As[a_col + 0][a_row] = av.x;
        As[a_col + 1][a_row] = av.y;
        As[a_col + 2][a_row] = av.z;
        As[a_col + 3][a_row] = av.w;
        float4 bv = *(const float4*)&B[(size_t)(k0 + b_row) * N_QKV + n0 + b_col];
        *(float4*)&Bs[b_row][b_col] = bv;
        __syncthreads();

#pragma unroll
        for (int k = 0; k < 8; k++) {
            float4 t0 = *(const float4*)&As[k][ty * 8];
            float4 t1 = *(const float4*)&As[k][ty * 8 + 4];
            double2 u0 = *(const double2*)&Bs[k][tx * 8];      // packed (b0,b1),(b2,b3)
            double2 u1 = *(const double2*)&Bs[k][tx * 8 + 4];  // packed (b4,b5),(b6,b7)
            double bp[4] = {u0.x, u0.y, u1.x, u1.y};
            float ar[8] = {t0.x, t0.y, t0.z, t0.w, t1.x, t1.y, t1.z, t1.w};
            double ad[8];
#pragma unroll
            for (int i = 0; i < 8; i++) ad[i] = fpack2(ar[i], ar[i]);
#pragma unroll
            for (int i = 0; i < 8; i++)
#pragma unroll
                for (int j = 0; j < 4; j++)
                    acc2[i][j] = ffma2(ad[i], bp[j], acc2[i][j]);
        }
        __syncthreads();
    }

    // Epilogue: scatter into head-major layout.
    const int col_base = n0 + tx * 8;
    const int sec = col_base >> 9;            // 0=Q,1=K,2=V
    const int inner = col_base & 511;
    const int h = inner >> 6;
    const int dh = inner & 63;
    float* dst = (sec == 0) ? g_Q : (sec == 1) ? g_K : g_V;
    const float mul = (sec == 0) ? ATT_SCALE : 1.0f;

#pragma unroll
    for (int i = 0; i < 8; i++) {
        int m = m0 + ty * 8 + i;
        int b = m >> 11;          // /2048
        int n = m & 2047;
        size_t base = ((size_t)((b << 3) + h) * NSEQ + n) * DHEAD + dh;
        float a0,a1,a2,a3,a4,a5,a6,a7;
        funpack2(acc2[i][0], a0, a1);
        funpack2(acc2[i][1], a2, a3);
        funpack2(acc2[i][2], a4, a5);
        funpack2(acc2[i][3], a6, a7);
        float4 v0, v1;
        v0.x = a0 * mul; v0.y = a1 * mul; v0.z = a2 * mul; v0.w = a3 * mul;
        v1.x = a4 * mul; v1.y = a5 * mul; v1.z = a6 * mul; v1.w = a7 * mul;
        *(float4*)&dst[base]     = v0;
        *(float4*)&dst[base + 4] = v1;
    }
}

// ---------------------------------------------------------------------------
// Kernel 2: flash attention (fp32, FFMA2 packed).
// Grid: (32 q-tiles, 32 bh). Block 256 threads = 16x16.
// Tile: 64 queries x 64 keys, d=64. Online softmax.
// ---------------------------------------------------------------------------
#define PITCH 68
#define ATT_SMEM_FLOATS (4 * 64 * PITCH)   // Qs,Ks,Vs,Ps
#define ATT_SMEM_BYTES  (ATT_SMEM_FLOATS * 4)

__global__ __launch_bounds__(256) void attn_kernel()
{
    extern __shared__ float sm[];
    float* Qs = sm;                   // [64][PITCH]  (row, d)
    float* Ks = sm + 64 * PITCH;      // [64][PITCH]  (key, d)
    float* Vs = sm + 2 * 64 * PITCH;  // [64][PITCH]  (key, dv)
    float* Ps = sm + 3 * 64 * PITCH;  // [64][PITCH]  TRANSPOSED: (key, row)

    const int tid = threadIdx.x;
    const int tx = tid & 15;
    const int ty = tid >> 4;
    const int r0 = ty * 4;
    const int c0 = tx * 4;

    const int bh = blockIdx.y;
    const int q0 = blockIdx.x * 64;
    const float* Qg = g_Q + (size_t)bh * NSEQ * DHEAD;
    const float* Kg = g_K + (size_t)bh * NSEQ * DHEAD;
    const float* Vg = g_V + (size_t)bh * NSEQ * DHEAD;

    // Load Q tile
    for (int i = tid; i < 1024; i += 256) {
        int r = i >> 4;
        int c = (i & 15) * 4;
        *(float4*)&Qs[r * PITCH + c] = *(const float4*)&Qg[(size_t)(q0 + r) * DHEAD + c];
    }

    float m_i[4], l_i[4];
    double o2[4][2];                  // O packed over j (4 cols = 2 pairs)
#pragma unroll
    for (int i = 0; i < 4; i++) {
        m_i[i] = -INFINITY;
        l_i[i] = 0.0f;
        o2[i][0] = 0.0;
        o2[i][1] = 0.0;
    }

    for (int kt = 0; kt < NSEQ / 64; kt++) {
        __syncthreads();   // previous iteration done with Ks/Vs/Ps
        const int k0 = kt * 64;
        for (int i = tid; i < 1024; i += 256) {
            int r = i >> 4;
            int c = (i & 15) * 4;
            *(float4*)&Ks[r * PITCH + c] = *(const float4*)&Kg[(size_t)(k0 + r) * DHEAD + c];
            *(float4*)&Vs[r * PITCH + c] = *(const float4*)&Vg[(size_t)(k0 + r) * DHEAD + c];
        }
        __syncthreads();

        // S = Q K^T, packed over the reduction dim d (even/odd partial sums).
        // Q,K rows are contiguous in d -> packed pairs load directly (no packs).
        double s2[4][4];
#pragma unroll
        for (int i = 0; i < 4; i++)
#pragma unroll
            for (int j = 0; j < 4; j++) s2[i][j] = 0.0;

#pragma unroll 4
        for (int d = 0; d < DHEAD; d += 4) {
            double2 q[4], k[4];
#pragma unroll
            for (int i = 0; i < 4; i++) q[i] = *(const double2*)&Qs[(r0 + i) * PITCH + d];
#pragma unroll
            for (int j = 0; j < 4; j++) k[j] = *(const double2*)&Ks[(c0 + j) * PITCH + d];
#pragma unroll
            for (int i = 0; i < 4; i++)
#pragma unroll
                for (int j = 0; j < 4; j++) {
                    s2[i][j] = ffma2(q[i].x, k[j].x, s2[i][j]);
                    s2[i][j] = ffma2(q[i].y, k[j].y, s2[i][j]);
                }
        }

        // Horizontal add of the packed partials
        float s[4][4];
#pragma unroll
        for (int i = 0; i < 4; i++)
#pragma unroll
            for (int j = 0; j < 4; j++) {
                float lo, hi;
                funpack2(s2[i][j], lo, hi);
                s[i][j] = lo + hi;
            }

        // Row max over 64 keys: local over 4 j, then across 16 lanes (same ty)
        float mt[4];
#pragma unroll
        for (int i = 0; i < 4; i++) {
            float m = fmaxf(fmaxf(s[i][0], s[i][1]), fmaxf(s[i][2], s[i][3]));
#pragma unroll
            for (int off = 8; off > 0; off >>= 1)
                m = fmaxf(m, __shfl_xor_sync(0xffffffffu, m, off));
            mt[i] = m;
        }

#pragma unroll
        for (int i = 0; i < 4; i++) {
            float m_new = fmaxf(m_i[i], mt[i]);
            float corr = __expf(m_i[i] - m_new);
            m_i[i] = m_new;
            float r = 0.0f;
#pragma unroll
            for (int j = 0; j < 4; j++) {
                s[i][j] = __expf(s[i][j] - m_new);
                r += s[i][j];
            }
#pragma unroll
            for (int off = 8; off > 0; off >>= 1)
                r += __shfl_xor_sync(0xffffffffu, r, off);
            l_i[i] = l_i[i] * corr + r;
            double cd = fpack2(corr, corr);
            o2[i][0] = fmul2(o2[i][0], cd);
            o2[i][1] = fmul2(o2[i][1], cd);
        }

        // Stage P transposed: Ps[key][row]
#pragma unroll
        for (int j = 0; j < 4; j++)
#pragma unroll
            for (int i = 0; i < 4; i++)
                Ps[(c0 + j) * PITCH + (r0 + i)] = s[i][j];
        __syncthreads();

        // O += P V  (packed over j: V pairs contiguous, P duplicated)
#pragma unroll 4
        for (int jk = 0; jk < 64; jk++) {
            float4 pv = *(const float4*)&Ps[jk * PITCH + r0];
            double2 vv = *(const double2*)&Vs[jk * PITCH + c0];
            double pd[4];
            pd[0] = fpack2(pv.x, pv.x);
            pd[1] = fpack2(pv.y, pv.y);
            pd[2] = fpack2(pv.z, pv.z);
            pd[3] = fpack2(pv.w, pv.w);
#pragma unroll
            for (int i = 0; i < 4; i++) {
                o2[i][0] = ffma2(pd[i], vv.x, o2[i][0]);
                o2[i][1] = ffma2(pd[i], vv.y, o2[i][1]);
            }
        }
    }

    // Normalize and write to g_O in [b*n][h*64+dh] layout
    const int b = bh >> 3;
    const int h = bh & 7;
#pragma unroll
    for (int i = 0; i < 4; i++) {
        float inv = 1.0f / l_i[i];
        int n = q0 + r0 + i;
        size_t base = ((size_t)(b * NSEQ + n)) * DIMX + h * DHEAD + c0;
        float o0, o1, o2f, o3;
        funpack2(o2[i][0], o0, o1);
        funpack2(o2[i][1], o2f, o3);
        float4 v;
        v.x = o0 * inv; v.y = o1 * inv;
        v.z = o2f * inv; v.w = o3 * inv;
        *(float4*)&g_O[base] = v;
    }
}

// ---------------------------------------------------------------------------
// Kernel 3: output projection  (A = g_O [8192,512], B = w_out [512,512]) + bias
// ---------------------------------------------------------------------------
__global__ __launch_bounds__(256) void out_gemm_kernel(
    const float* __restrict__ B, const float* __restrict__ bias,
    float* __restrict__ out)
{
    __shared__ float As[8][128];
    __shared__ float Bs[8][128];

    const int tid = threadIdx.x;
    const int m0 = blockIdx.y * 128;
    const int n0 = blockIdx.x * 128;
    const int tx = tid & 15;
    const int ty = tid >> 4;

    const int a_row = tid >> 1;
    const int a_col = (tid & 1) * 4;
    const int b_row = tid >> 5;
    const int b_col = (tid & 31) * 4;

    double acc2[8][4];
#pragma unroll
    for (int i = 0; i < 8; i++)
#pragma unroll
        for (int j = 0; j < 4; j++) acc2[i][j] = 0.0;

    const float* A = g_O;
    for (int k0 = 0; k0 < DIMX; k0 += 8) {
        float4 av = *(const float4*)&A[(size_t)(m0 + a_row) * DIMX + k0 + a_col];
        As[a_col + 0][a_row] = av.x;
        As[a_col + 1][a_row] = av.y;
        As[a_col + 2][a_row] = av.z;
        As[a_col + 3][a_row] = av.w;
        float4 bv = *(const float4*)&B[(size_t)(k0 + b_row) * DIMX + n0 + b_col];
        *(float4*)&Bs[b_row][b_col] = bv;
        __syncthreads();

#pragma unroll
        for (int k = 0; k < 8; k++) {
            float4 t0 = *(const float4*)&As[k][ty * 8];
            float4 t1 = *(const float4*)&As[k][ty * 8 + 4];
            double2 u0 = *(const double2*)&Bs[k][tx * 8];
            double2 u1 = *(const double2*)&Bs[k][tx * 8 + 4];
            double bp[4] = {u0.x, u0.y, u1.x, u1.y};
            float ar[8] = {t0.x, t0.y, t0.z, t0.w, t1.x, t1.y, t1.z, t1.w};
            double ad[8];
#pragma unroll
            for (int i = 0; i < 8; i++) ad[i] = fpack2(ar[i], ar[i]);
#pragma unroll
            for (int i = 0; i < 8; i++)
#pragma unroll
                for (int j = 0; j < 4; j++)
                    acc2[i][j] = ffma2(ad[i], bp[j], acc2[i][j]);
        }
        __syncthreads();
    }

    const int col = n0 + tx * 8;
    float bb[8];
#pragma unroll
    for (int j = 0; j < 8; j++) bb[j] = bias[col + j];

#pragma unroll
    for (int i = 0; i < 8; i++) {
        int m = m0 + ty * 8 + i;
        float a0,a1,a2,a3,a4,a5,a6,a7;
        funpack2(acc2[i][0], a0, a1);
        funpack2(acc2[i][1], a2, a3);
        funpack2(acc2[i][2], a4, a5);
        funpack2(acc2[i][3], a6, a7);
        float4 v0, v1;
        v0.x = a0 + bb[0]; v0.y = a1 + bb[1];
        v0.z = a2 + bb[2]; v0.w = a3 + bb[3];
        v1.x = a4 + bb[4]; v1.y = a5 + bb[5];
        v1.z = a6 + bb[6]; v1.w = a7 + bb[7];
        *(float4*)&out[(size_t)m * DIMX + col]     = v0;
        *(float4*)&out[(size_t)m * DIMX + col + 4] = v1;
    }
}

// ---------------------------------------------------------------------------
extern "C" void kernel_launch(void* const* d_in, const int* in_sizes, int n_in,
                              void* d_out, int out_size)
{
    const float* x     = (const float*)d_in[0];  // [4,2048,512]
    const float* w_qkv = (const float*)d_in[1];  // [512,1536]
    const float* w_out = (const float*)d_in[2];  // [512,512]
    const float* b_out = (const float*)d_in[3];  // [512]
    float* out = (float*)d_out;

    cudaFuncSetAttribute(attn_kernel,
                         cudaFuncAttributeMaxDynamicSharedMemorySize,
                         ATT_SMEM_BYTES);

    qkv_gemm_kernel<<<dim3(N_QKV / 128, M_ROWS / 128), 256>>>(x, w_qkv);
    attn_kernel<<<dim3(NSEQ / 64, BATCH * HEADS), 256, ATT_SMEM_BYTES>>>();
    out_gemm_kernel<<<dim3(DIMX / 128, M_ROWS / 128), 256>>>(w_out, b_out, out);
}

// round 4
// speedup vs baseline: 2.7463x; 2.7463x over previous
#include <cuda_runtime.h>
#include <math.h>

// Problem constants
#define BATCH 4
#define NSEQ  2048
#define DIMX  512
#define HEADS 8
#define DHEAD 64
#define M_ROWS (BATCH * NSEQ)      // 8192
#define N_QKV  (3 * DIMX)          // 1536
#define ATT_SCALE 0.125f           // 64^-0.5

// Scratch (device globals; no runtime allocation allowed)
__device__ float g_Q[BATCH * HEADS * NSEQ * DHEAD];  // [bh][n][64], pre-scaled
__device__ float g_K[BATCH * HEADS * NSEQ * DHEAD];
__device__ float g_V[BATCH * HEADS * NSEQ * DHEAD];
__device__ float g_O[M_ROWS * DIMX];                 // [b*n][h*64+dh]

// ---------------------------------------------------------------------------
// TF32 helpers
// ---------------------------------------------------------------------------
__device__ __forceinline__ unsigned f2tf(float f) {
    unsigned u;
    asm("cvt.rna.tf32.f32 %0, %1;" : "=r"(u) : "f"(f));
    return u;
}
// D = A(16x8,row) * B(8x8,col) + D, tf32 in, fp32 accum
__device__ __forceinline__ void mma_tf32(float* c, const unsigned* a,
                                         unsigned b0, unsigned b1) {
    asm volatile(
        "mma.sync.aligned.m16n8k8.row.col.f32.tf32.tf32.f32 "
        "{%0,%1,%2,%3}, {%4,%5,%6,%7}, {%8,%9}, {%0,%1,%2,%3};"
        : "+f"(c[0]), "+f"(c[1]), "+f"(c[2]), "+f"(c[3])
        : "r"(a[0]), "r"(a[1]), "r"(a[2]), "r"(a[3]), "r"(b0), "r"(b1));
}

// ---------------------------------------------------------------------------
// Kernel 1: QKV GEMM (scalar fp32, proven R1 version)
// ---------------------------------------------------------------------------
__global__ __launch_bounds__(256) void qkv_gemm_kernel(
    const float* __restrict__ A, const float* __restrict__ B)
{
    __shared__ float As[8][128];
    __shared__ float Bs[8][128];

    const int tid = threadIdx.x;
    const int m0 = blockIdx.y * 128;
    const int n0 = blockIdx.x * 128;
    const int tx = tid & 15;
    const int ty = tid >> 4;

    const int a_row = tid >> 1;
    const int a_col = (tid & 1) * 4;
    const int b_row = tid >> 5;
    const int b_col = (tid & 31) * 4;

    float acc[8][8];
#pragma unroll
    for (int i = 0; i < 8; i++)
#pragma unroll
        for (int j = 0; j < 8; j++) acc[i][j] = 0.0f;

    for (int k0 = 0; k0 < DIMX; k0 += 8) {
        float4 av = *(const float4*)&A[(size_t)(m0 + a_row) * DIMX + k0 + a_col];
        As[a_col + 0][a_row] = av.x;
        As[a_col + 1][a_row] = av.y;
        As[a_col + 2][a_row] = av.z;
        As[a_col + 3][a_row] = av.w;
        float4 bv = *(const float4*)&B[(size_t)(k0 + b_row) * N_QKV + n0 + b_col];
        *(float4*)&Bs[b_row][b_col] = bv;
        __syncthreads();

#pragma unroll
        for (int k = 0; k < 8; k++) {
            float ar[8], br[8];
            float4 t0 = *(const float4*)&As[k][ty * 8];
            float4 t1 = *(const float4*)&As[k][ty * 8 + 4];
            ar[0]=t0.x; ar[1]=t0.y; ar[2]=t0.z; ar[3]=t0.w;
            ar[4]=t1.x; ar[5]=t1.y; ar[6]=t1.z; ar[7]=t1.w;
            float4 u0 = *(const float4*)&Bs[k][tx * 8];
            float4 u1 = *(const float4*)&Bs[k][tx * 8 + 4];
            br[0]=u0.x; br[1]=u0.y; br[2]=u0.z; br[3]=u0.w;
            br[4]=u1.x; br[5]=u1.y; br[6]=u1.z; br[7]=u1.w;
#pragma unroll
            for (int i = 0; i < 8; i++)
#pragma unroll
                for (int j = 0; j < 8; j++)
                    acc[i][j] = fmaf(ar[i], br[j], acc[i][j]);
        }
        __syncthreads();
    }

    const int col_base = n0 + tx * 8;
    const int sec = col_base >> 9;            // 0=Q,1=K,2=V
    const int inner = col_base & 511;
    const int h = inner >> 6;
    const int dh = inner & 63;
    float* dst = (sec == 0) ? g_Q : (sec == 1) ? g_K : g_V;
    const float mul = (sec == 0) ? ATT_SCALE : 1.0f;

#pragma unroll
    for (int i = 0; i < 8; i++) {
        int m = m0 + ty * 8 + i;
        int b = m >> 11;
        int n = m & 2047;
        size_t base = ((size_t)((b << 3) + h) * NSEQ + n) * DHEAD + dh;
        float4 v0, v1;
        v0.x = acc[i][0] * mul; v0.y = acc[i][1] * mul;
        v0.z = acc[i][2] * mul; v0.w = acc[i][3] * mul;
        v1.x = acc[i][4] * mul; v1.y = acc[i][5] * mul;
        v1.z = acc[i][6] * mul; v1.w = acc[i][7] * mul;
        *(float4*)&dst[base]     = v0;
        *(float4*)&dst[base + 4] = v1;
    }
}

// ---------------------------------------------------------------------------
// Kernel 2: flash attention with TF32 mma.sync (m16n8k8).
// Block: 128 threads / 4 warps. BM=64 (warp: m16 x n64), BN=64, d=64.
// smem (uint, pitch 68):
//   sA: Q staging then per-warp P slices [16][68] each
//   sK: K tile natural [key][d]
//   sV: V tile transposed [d][key]
// ---------------------------------------------------------------------------
#define APITCH 68
#define ATT_SMEM_BYTES (3 * 64 * APITCH * 4)

__global__ __launch_bounds__(128) void attn_tc_kernel()
{
    extern __shared__ unsigned smu[];
    unsigned* sA = smu;                  // 64*68
    unsigned* sK = smu + 64 * APITCH;
    unsigned* sV = smu + 2 * 64 * APITCH;

    const int tid  = threadIdx.x;
    const int lane = tid & 31;
    const int w    = tid >> 5;
    const int g    = lane >> 2;   // 0..7
    const int tig  = lane & 3;    // 0..3

    const int bh = blockIdx.y;
    const int q0 = blockIdx.x * 64;
    const float* Qg = g_Q + (size_t)bh * NSEQ * DHEAD;
    const float* Kg = g_K + (size_t)bh * NSEQ * DHEAD;
    const float* Vg = g_V + (size_t)bh * NSEQ * DHEAD;

    // ---- Stage Q (tf32) and extract per-warp A fragments ----
    for (int i = tid; i < 1024; i += 128) {
        int r = i >> 4;
        int c = (i & 15) * 4;
        float4 v = *(const float4*)&Qg[(size_t)(q0 + r) * DHEAD + c];
        uint4 u;
        u.x = f2tf(v.x); u.y = f2tf(v.y); u.z = f2tf(v.z); u.w = f2tf(v.w);
        *(uint4*)&sA[r * APITCH + c] = u;
    }
    __syncthreads();

    unsigned qa[8][4];
    const int mrow = w * 16 + g;
#pragma unroll
    for (int kk = 0; kk < 8; kk++) {
        qa[kk][0] = sA[mrow * APITCH + kk * 8 + tig];
        qa[kk][1] = sA[(mrow + 8) * APITCH + kk * 8 + tig];
        qa[kk][2] = sA[mrow * APITCH + kk * 8 + tig + 4];
        qa[kk][3] = sA[(mrow + 8) * APITCH + kk * 8 + tig + 4];
    }
    unsigned* sP = sA + w * 16 * APITCH;   // per-warp slice

    float oc[8][4];
#pragma unroll
    for (int dn = 0; dn < 8; dn++)
#pragma unroll
        for (int j = 0; j < 4; j++) oc[dn][j] = 0.0f;
    float m0 = -INFINITY, m1 = -INFINITY, l0 = 0.0f, l1 = 0.0f;

    for (int kt = 0; kt < NSEQ / 64; kt++) {
        __syncthreads();   // all warps done reading sK/sV (and Q extraction)
        const int k0 = kt * 64;
        for (int i = tid; i < 1024; i += 128) {
            int r = i >> 4;
            int c = (i & 15) * 4;
            float4 kv = *(const float4*)&Kg[(size_t)(k0 + r) * DHEAD + c];
            uint4 ku;
            ku.x = f2tf(kv.x); ku.y = f2tf(kv.y); ku.z = f2tf(kv.z); ku.w = f2tf(kv.w);
            *(uint4*)&sK[r * APITCH + c] = ku;
            float4 vv = *(const float4*)&Vg[(size_t)(k0 + r) * DHEAD + c];
            sV[(c + 0) * APITCH + r] = f2tf(vv.x);
            sV[(c + 1) * APITCH + r] = f2tf(vv.y);
            sV[(c + 2) * APITCH + r] = f2tf(vv.z);
            sV[(c + 3) * APITCH + r] = f2tf(vv.w);
        }
        __syncthreads();

        // ---- S = Q K^T ----
        float sc[8][4];
#pragma unroll
        for (int n = 0; n < 8; n++)
#pragma unroll
            for (int j = 0; j < 4; j++) sc[n][j] = 0.0f;

#pragma unroll
        for (int kk = 0; kk < 8; kk++) {
#pragma unroll
            for (int n = 0; n < 8; n++) {
                unsigned b0 = sK[(n * 8 + g) * APITCH + kk * 8 + tig];
                unsigned b1 = sK[(n * 8 + g) * APITCH + kk * 8 + tig + 4];
                mma_tf32(sc[n], qa[kk], b0, b1);
            }
        }

        // ---- online softmax (rows g and g+8) ----
        float mx0 = -INFINITY, mx1 = -INFINITY;
#pragma unroll
        for (int n = 0; n < 8; n++) {
            mx0 = fmaxf(mx0, fmaxf(sc[n][0], sc[n][1]));
            mx1 = fmaxf(mx1, fmaxf(sc[n][2], sc[n][3]));
        }
        mx0 = fmaxf(mx0, __shfl_xor_sync(0xffffffffu, mx0, 1));
        mx0 = fmaxf(mx0, __shfl_xor_sync(0xffffffffu, mx0, 2));
        mx1 = fmaxf(mx1, __shfl_xor_sync(0xffffffffu, mx1, 1));
        mx1 = fmaxf(mx1, __shfl_xor_sync(0xffffffffu, mx1, 2));

        float nm0 = fmaxf(m0, mx0);
        float nm1 = fmaxf(m1, mx1);
        float cr0 = __expf(m0 - nm0);
        float cr1 = __expf(m1 - nm1);
        m0 = nm0; m1 = nm1;

        float r0 = 0.0f, r1 = 0.0f;
#pragma unroll
        for (int n = 0; n < 8; n++) {
            float e00 = __expf(sc[n][0] - nm0);
            float e01 = __expf(sc[n][1] - nm0);
            float e10 = __expf(sc[n][2] - nm1);
            float e11 = __expf(sc[n][3] - nm1);
            r0 += e00 + e01;
            r1 += e10 + e11;
            uint2 p0; p0.x = f2tf(e00); p0.y = f2tf(e01);
            uint2 p1; p1.x = f2tf(e10); p1.y = f2tf(e11);
            *(uint2*)&sP[g * APITCH + n * 8 + 2 * tig]       = p0;
            *(uint2*)&sP[(g + 8) * APITCH + n * 8 + 2 * tig] = p1;
        }
        r0 += __shfl_xor_sync(0xffffffffu, r0, 1);
        r0 += __shfl_xor_sync(0xffffffffu, r0, 2);
        r1 += __shfl_xor_sync(0xffffffffu, r1, 1);
        r1 += __shfl_xor_sync(0xffffffffu, r1, 2);
        l0 = l0 * cr0 + r0;
        l1 = l1 * cr1 + r1;
#pragma unroll
        for (int dn = 0; dn < 8; dn++) {
            oc[dn][0] *= cr0; oc[dn][1] *= cr0;
            oc[dn][2] *= cr1; oc[dn][3] *= cr1;
        }
        __syncwarp();

        // ---- O += P V ----
#pragma unroll
        for (int kk = 0; kk < 8; kk++) {
            unsigned pa[4];
            pa[0] = sP[g * APITCH + kk * 8 + tig];
            pa[1] = sP[(g + 8) * APITCH + kk * 8 + tig];
            pa[2] = sP[g * APITCH + kk * 8 + tig + 4];
            pa[3] = sP[(g + 8) * APITCH + kk * 8 + tig + 4];
#pragma unroll
            for (int dn = 0; dn < 8; dn++) {
                unsigned b0 = sV[(dn * 8 + g) * APITCH + kk * 8 + tig];
                unsigned b1 = sV[(dn * 8 + g) * APITCH + kk * 8 + tig + 4];
                mma_tf32(oc[dn], pa, b0, b1);
            }
        }
    }

    // ---- epilogue: normalize, write g_O [b*n][h*64+d] ----
    const int b = bh >> 3;
    const int h = bh & 7;
    const float inv0 = 1.0f / l0;
    const float inv1 = 1.0f / l1;
    const int row0 = q0 + w * 16 + g;
    const int row1 = row0 + 8;
    float* O0 = &g_O[((size_t)(b * NSEQ + row0)) * DIMX + h * DHEAD];
    float* O1 = &g_O[((size_t)(b * NSEQ + row1)) * DIMX + h * DHEAD];
#pragma unroll
    for (int dn = 0; dn < 8; dn++) {
        int c = dn * 8 + 2 * tig;
        float2 v0; v0.x = oc[dn][0] * inv0; v0.y = oc[dn][1] * inv0;
        float2 v1; v1.x = oc[dn][2] * inv1; v1.y = oc[dn][3] * inv1;
        *(float2*)&O0[c] = v0;
        *(float2*)&O1[c] = v1;
    }
}

// ---------------------------------------------------------------------------
// Kernel 3: output projection (scalar fp32, proven R1 version)
// ---------------------------------------------------------------------------
__global__ __launch_bounds__(256) void out_gemm_kernel(
    const float* __restrict__ B, const float* __restrict__ bias,
    float* __restrict__ out)
{
    __shared__ float As[8][128];
    __shared__ float Bs[8][128];

    const int tid = threadIdx.x;
    const int m0 = blockIdx.y * 128;
    const int n0 = blockIdx.x * 128;
    const int tx = tid & 15;
    const int ty = tid >> 4;

    const int a_row = tid >> 1;
    const int a_col = (tid & 1) * 4;
    const int b_row = tid >> 5;
    const int b_col = (tid & 31) * 4;

    float acc[8][8];
#pragma unroll
    for (int i = 0; i < 8; i++)
#pragma unroll
        for (int j = 0; j < 8; j++) acc[i][j] = 0.0f;

    const float* A = g_O;
    for (int k0 = 0; k0 < DIMX; k0 += 8) {
        float4 av = *(const float4*)&A[(size_t)(m0 + a_row) * DIMX + k0 + a_col];
        As[a_col + 0][a_row] = av.x;
        As[a_col + 1][a_row] = av.y;
        As[a_col + 2][a_row] = av.z;
        As[a_col + 3][a_row] = av.w;
        float4 bv = *(const float4*)&B[(size_t)(k0 + b_row) * DIMX + n0 + b_col];
        *(float4*)&Bs[b_row][b_col] = bv;
        __syncthreads();

#pragma unroll
        for (int k = 0; k < 8; k++) {
            float ar[8], br[8];
            float4 t0 = *(const float4*)&As[k][ty * 8];
            float4 t1 = *(const float4*)&As[k][ty * 8 + 4];
            ar[0]=t0.x; ar[1]=t0.y; ar[2]=t0.z; ar[3]=t0.w;
            ar[4]=t1.x; ar[5]=t1.y; ar[6]=t1.z; ar[7]=t1.w;
            float4 u0 = *(const float4*)&Bs[k][tx * 8];
            float4 u1 = *(const float4*)&Bs[k][tx * 8 + 4];
            br[0]=u0.x; br[1]=u0.y; br[2]=u0.z; br[3]=u0.w;
            br[4]=u1.x; br[5]=u1.y; br[6]=u1.z; br[7]=u1.w;
#pragma unroll
            for (int i = 0; i < 8; i++)
#pragma unroll
                for (int j = 0; j < 8; j++)
                    acc[i][j] = fmaf(ar[i], br[j], acc[i][j]);
        }
        __syncthreads();
    }

    const int col = n0 + tx * 8;
    float bb[8];
#pragma unroll
    for (int j = 0; j < 8; j++) bb[j] = bias[col + j];

#pragma unroll
    for (int i = 0; i < 8; i++) {
        int m = m0 + ty * 8 + i;
        float4 v0, v1;
        v0.x = acc[i][0] + bb[0]; v0.y = acc[i][1] + bb[1];
        v0.z = acc[i][2] + bb[2]; v0.w = acc[i][3] + bb[3];
        v1.x = acc[i][4] + bb[4]; v1.y = acc[i][5] + bb[5];
        v1.z = acc[i][6] + bb[6]; v1.w = acc[i][7] + bb[7];
        *(float4*)&out[(size_t)m * DIMX + col]     = v0;
        *(float4*)&out[(size_t)m * DIMX + col + 4] = v1;
    }
}

// ---------------------------------------------------------------------------
extern "C" void kernel_launch(void* const* d_in, const int* in_sizes, int n_in,
                              void* d_out, int out_size)
{
    const float* x     = (const float*)d_in[0];  // [4,2048,512]
    const float* w_qkv = (const float*)d_in[1];  // [512,1536]
    const float* w_out = (const float*)d_in[2];  // [512,512]
    const float* b_out = (const float*)d_in[3];  // [512]
    float* out = (float*)d_out;

    cudaFuncSetAttribute(attn_tc_kernel,
                         cudaFuncAttributeMaxDynamicSharedMemorySize,
                         ATT_SMEM_BYTES);

    qkv_gemm_kernel<<<dim3(N_QKV / 128, M_ROWS / 128), 256>>>(x, w_qkv);
    attn_tc_kernel<<<dim3(NSEQ / 64, BATCH * HEADS), 128, ATT_SMEM_BYTES>>>();
    out_gemm_kernel<<<dim3(DIMX / 128, M_ROWS / 128), 256>>>(w_out, b_out, out);
}

// round 5
// speedup vs baseline: 3.9090x; 1.4234x over previous
#include <cuda_runtime.h>
#include <math.h>

// Problem constants
#define BATCH 4
#define NSEQ  2048
#define DIMX  512
#define HEADS 8
#define DHEAD 64
#define M_ROWS (BATCH * NSEQ)      // 8192
#define N_QKV  (3 * DIMX)          // 1536
#define ATT_SCALE 0.125f           // 64^-0.5

// Scratch (device globals; no runtime allocation allowed)
__device__ float g_Q[BATCH * HEADS * NSEQ * DHEAD];  // [bh][n][64], pre-scaled
__device__ float g_K[BATCH * HEADS * NSEQ * DHEAD];
__device__ float g_V[BATCH * HEADS * NSEQ * DHEAD];
__device__ float g_O[M_ROWS * DIMX];                 // [b*n][h*64+dh]

// ---------------------------------------------------------------------------
// TF32 helpers
// ---------------------------------------------------------------------------
__device__ __forceinline__ unsigned f2tf(float f) {
    unsigned u;
    asm("cvt.rna.tf32.f32 %0, %1;" : "=r"(u) : "f"(f));
    return u;
}
// D = A(16x8,row) * B(8x8,col) + D, tf32 in, fp32 accum
__device__ __forceinline__ void mma_tf32(float* c, const unsigned* a,
                                         unsigned b0, unsigned b1) {
    asm volatile(
        "mma.sync.aligned.m16n8k8.row.col.f32.tf32.tf32.f32 "
        "{%0,%1,%2,%3}, {%4,%5,%6,%7}, {%8,%9}, {%0,%1,%2,%3};"
        : "+f"(c[0]), "+f"(c[1]), "+f"(c[2]), "+f"(c[3])
        : "r"(a[0]), "r"(a[1]), "r"(a[2]), "r"(a[3]), "r"(b0), "r"(b1));
}

// ---------------------------------------------------------------------------
// TF32 GEMM core (shared by kernels 1 and 3).
// BM=128, BN=128, BK=16. 256 threads / 8 warps (2 m x 4 n), warp tile 64x32.
// As[k][m] pitch TP, Bs[k][n] pitch TP. Fragment mappings identical to the
// validated attention kernel.
// ---------------------------------------------------------------------------
#define TP 132

struct GemmFrag {
    float acc[4][4][4];   // [mf][nf][reg]
};

// Runs the K-loop, leaves results in fr.acc. ldb = row stride of B (elements).
__device__ __forceinline__ void tf32_gemm_core(
    const float* __restrict__ A, const float* __restrict__ B,
    int m0, int n0, int ldb, int kdim,
    unsigned* As, unsigned* Bs, GemmFrag& fr)
{
    const int tid  = threadIdx.x;
    const int lane = tid & 31;
    const int w    = tid >> 5;
    const int g    = lane >> 2;
    const int tig  = lane & 3;
    const int mw   = (w >> 2) * 64;
    const int nw   = (w & 3) * 32;

#pragma unroll
    for (int mf = 0; mf < 4; mf++)
#pragma unroll
        for (int nf = 0; nf < 4; nf++)
#pragma unroll
            for (int r = 0; r < 4; r++) fr.acc[mf][nf][r] = 0.0f;

    const int ar = tid >> 2;            // A fill: row 0..63 (+64 second pass)
    const int ac = (tid & 3) * 4;       // A fill: k col 0,4,8,12
    const int bkr = tid >> 5;           // B fill: k row 0..7 (+8 second pass)
    const int bnc = (tid & 31) * 4;     // B fill: n col

    for (int k0 = 0; k0 < kdim; k0 += 16) {
        // Fill As[k][m] (transpose; scalar STS, ~2-way)
#pragma unroll
        for (int s = 0; s < 2; s++) {
            int r = ar + s * 64;
            float4 v = *(const float4*)&A[(size_t)(m0 + r) * kdim + k0 + ac];
            As[(ac + 0) * TP + r] = f2tf(v.x);
            As[(ac + 1) * TP + r] = f2tf(v.y);
            As[(ac + 2) * TP + r] = f2tf(v.z);
            As[(ac + 3) * TP + r] = f2tf(v.w);
        }
        // Fill Bs[k][n] (natural; vector STS, conflict-free)
#pragma unroll
        for (int s = 0; s < 2; s++) {
            int kr = bkr + s * 8;
            float4 v = *(const float4*)&B[(size_t)(k0 + kr) * ldb + n0 + bnc];
            uint4 u;
            u.x = f2tf(v.x); u.y = f2tf(v.y); u.z = f2tf(v.z); u.w = f2tf(v.w);
            *(uint4*)&Bs[kr * TP + bnc] = u;
        }
        __syncthreads();

#pragma unroll
        for (int kk = 0; kk < 2; kk++) {
            const int kb = kk * 8;
            unsigned a[4][4];
#pragma unroll
            for (int mf = 0; mf < 4; mf++) {
                int mc = mw + mf * 16 + g;
                a[mf][0] = As[(kb + tig) * TP + mc];
                a[mf][1] = As[(kb + tig) * TP + mc + 8];
                a[mf][2] = As[(kb + tig + 4) * TP + mc];
                a[mf][3] = As[(kb + tig + 4) * TP + mc + 8];
            }
            unsigned b0[4], b1[4];
#pragma unroll
            for (int nf = 0; nf < 4; nf++) {
                int nc = nw + nf * 8 + g;
                b0[nf] = Bs[(kb + tig) * TP + nc];
                b1[nf] = Bs[(kb + tig + 4) * TP + nc];
            }
#pragma unroll
            for (int mf = 0; mf < 4; mf++)
#pragma unroll
                for (int nf = 0; nf < 4; nf++)
                    mma_tf32(fr.acc[mf][nf], a[mf], b0[nf], b1[nf]);
        }
        __syncthreads();
    }
}

// ---------------------------------------------------------------------------
// Kernel 1: QKV GEMM, TF32.  A = x [8192,512], B = w_qkv [512,1536].
// Epilogue scatters into head-major Q/K/V, folding ATT_SCALE into Q.
// ---------------------------------------------------------------------------
__global__ __launch_bounds__(256) void qkv_gemm_tf32_kernel(
    const float* __restrict__ A, const float* __restrict__ B)
{
    __shared__ unsigned As[16 * TP];
    __shared__ unsigned Bs[16 * TP];

    const int m0 = blockIdx.y * 128;
    const int n0 = blockIdx.x * 128;
    GemmFrag fr;
    tf32_gemm_core(A, B, m0, n0, N_QKV, DIMX, As, Bs, fr);

    const int lane = threadIdx.x & 31;
    const int w    = threadIdx.x >> 5;
    const int g    = lane >> 2;
    const int tig  = lane & 3;
    const int mw   = (w >> 2) * 64;
    const int nw   = (w & 3) * 32;

    const int sec = n0 >> 9;                  // whole block in one section
    float* dst = (sec == 0) ? g_Q : (sec == 1) ? g_K : g_V;
    const float mul = (sec == 0) ? ATT_SCALE : 1.0f;
    const int ninner0 = n0 & 511;

#pragma unroll
    for (int mf = 0; mf < 4; mf++) {
#pragma unroll
        for (int nf = 0; nf < 4; nf++) {
            int col = ninner0 + nw + nf * 8 + 2 * tig;
            int h = col >> 6;
            int dh = col & 63;
#pragma unroll
            for (int half = 0; half < 2; half++) {
                int m = m0 + mw + mf * 16 + g + half * 8;
                int b = m >> 11;
                int n = m & 2047;
                size_t base = ((size_t)((b << 3) + h) * NSEQ + n) * DHEAD + dh;
                float2 v;
                v.x = fr.acc[mf][nf][2 * half + 0] * mul;
                v.y = fr.acc[mf][nf][2 * half + 1] * mul;
                *(float2*)&dst[base] = v;
            }
        }
    }
}

// ---------------------------------------------------------------------------
// Kernel 3: output projection, TF32. A = g_O [8192,512], B = w_out [512,512].
// ---------------------------------------------------------------------------
__global__ __launch_bounds__(256) void out_gemm_tf32_kernel(
    const float* __restrict__ B, const float* __restrict__ bias,
    float* __restrict__ out)
{
    __shared__ unsigned As[16 * TP];
    __shared__ unsigned Bs[16 * TP];

    const int m0 = blockIdx.y * 128;
    const int n0 = blockIdx.x * 128;
    GemmFrag fr;
    tf32_gemm_core(g_O, B, m0, n0, DIMX, DIMX, As, Bs, fr);

    const int lane = threadIdx.x & 31;
    const int w    = threadIdx.x >> 5;
    const int g    = lane >> 2;
    const int tig  = lane & 3;
    const int mw   = (w >> 2) * 64;
    const int nw   = (w & 3) * 32;

#pragma unroll
    for (int mf = 0; mf < 4; mf++) {
#pragma unroll
        for (int nf = 0; nf < 4; nf++) {
            int col = n0 + nw + nf * 8 + 2 * tig;
            float bx = bias[col];
            float by = bias[col + 1];
#pragma unroll
            for (int half = 0; half < 2; half++) {
                int m = m0 + mw + mf * 16 + g + half * 8;
                float2 v;
                v.x = fr.acc[mf][nf][2 * half + 0] + bx;
                v.y = fr.acc[mf][nf][2 * half + 1] + by;
                *(float2*)&out[(size_t)m * DIMX + col] = v;
            }
        }
    }
}

// ---------------------------------------------------------------------------
// Kernel 2: flash attention with TF32 mma.sync (m16n8k8) — unchanged from R4.
// ---------------------------------------------------------------------------
#define APITCH 68
#define ATT_SMEM_BYTES (3 * 64 * APITCH * 4)

__global__ __launch_bounds__(128) void attn_tc_kernel()
{
    extern __shared__ unsigned smu[];
    unsigned* sA = smu;                  // 64*68
    unsigned* sK = smu + 64 * APITCH;
    unsigned* sV = smu + 2 * 64 * APITCH;

    const int tid  = threadIdx.x;
    const int lane = tid & 31;
    const int w    = tid >> 5;
    const int g    = lane >> 2;   // 0..7
    const int tig  = lane & 3;    // 0..3

    const int bh = blockIdx.y;
    const int q0 = blockIdx.x * 64;
    const float* Qg = g_Q + (size_t)bh * NSEQ * DHEAD;
    const float* Kg = g_K + (size_t)bh * NSEQ * DHEAD;
    const float* Vg = g_V + (size_t)bh * NSEQ * DHEAD;

    // ---- Stage Q (tf32) and extract per-warp A fragments ----
    for (int i = tid; i < 1024; i += 128) {
        int r = i >> 4;
        int c = (i & 15) * 4;
        float4 v = *(const float4*)&Qg[(size_t)(q0 + r) * DHEAD + c];
        uint4 u;
        u.x = f2tf(v.x); u.y = f2tf(v.y); u.z = f2tf(v.z); u.w = f2tf(v.w);
        *(uint4*)&sA[r * APITCH + c] = u;
    }
    __syncthreads();

    unsigned qa[8][4];
    const int mrow = w * 16 + g;
#pragma unroll
    for (int kk = 0; kk < 8; kk++) {
        qa[kk][0] = sA[mrow * APITCH + kk * 8 + tig];
        qa[kk][1] = sA[(mrow + 8) * APITCH + kk * 8 + tig];
        qa[kk][2] = sA[mrow * APITCH + kk * 8 + tig + 4];
        qa[kk][3] = sA[(mrow + 8) * APITCH + kk * 8 + tig + 4];
    }
    unsigned* sP = sA + w * 16 * APITCH;   // per-warp slice

    float oc[8][4];
#pragma unroll
    for (int dn = 0; dn < 8; dn++)
#pragma unroll
        for (int j = 0; j < 4; j++) oc[dn][j] = 0.0f;
    float m0 = -INFINITY, m1 = -INFINITY, l0 = 0.0f, l1 = 0.0f;

    for (int kt = 0; kt < NSEQ / 64; kt++) {
        __syncthreads();   // all warps done reading sK/sV (and Q extraction)
        const int k0 = kt * 64;
        for (int i = tid; i < 1024; i += 128) {
            int r = i >> 4;
            int c = (i & 15) * 4;
            float4 kv = *(const float4*)&Kg[(size_t)(k0 + r) * DHEAD + c];
            uint4 ku;
            ku.x = f2tf(kv.x); ku.y = f2tf(kv.y); ku.z = f2tf(kv.z); ku.w = f2tf(kv.w);
            *(uint4*)&sK[r * APITCH + c] = ku;
            float4 vv = *(const float4*)&Vg[(size_t)(k0 + r) * DHEAD + c];
            sV[(c + 0) * APITCH + r] = f2tf(vv.x);
            sV[(c + 1) * APITCH + r] = f2tf(vv.y);
            sV[(c + 2) * APITCH + r] = f2tf(vv.z);
            sV[(c + 3) * APITCH + r] = f2tf(vv.w);
        }
        __syncthreads();

        // ---- S = Q K^T ----
        float sc[8][4];
#pragma unroll
        for (int n = 0; n < 8; n++)
#pragma unroll
            for (int j = 0; j < 4; j++) sc[n][j] = 0.0f;

#pragma unroll
        for (int kk = 0; kk < 8; kk++) {
#pragma unroll
            for (int n = 0; n < 8; n++) {
                unsigned b0 = sK[(n * 8 + g) * APITCH + kk * 8 + tig];
                unsigned b1 = sK[(n * 8 + g) * APITCH + kk * 8 + tig + 4];
                mma_tf32(sc[n], qa[kk], b0, b1);
            }
        }

        // ---- online softmax (rows g and g+8) ----
        float mx0 = -INFINITY, mx1 = -INFINITY;
#pragma unroll
        for (int n = 0; n < 8; n++) {
            mx0 = fmaxf(mx0, fmaxf(sc[n][0], sc[n][1]));
            mx1 = fmaxf(mx1, fmaxf(sc[n][2], sc[n][3]));
        }
        mx0 = fmaxf(mx0, __shfl_xor_sync(0xffffffffu, mx0, 1));
        mx0 = fmaxf(mx0, __shfl_xor_sync(0xffffffffu, mx0, 2));
        mx1 = fmaxf(mx1, __shfl_xor_sync(0xffffffffu, mx1, 1));
        mx1 = fmaxf(mx1, __shfl_xor_sync(0xffffffffu, mx1, 2));

        float nm0 = fmaxf(m0, mx0);
        float nm1 = fmaxf(m1, mx1);
        float cr0 = __expf(m0 - nm0);
        float cr1 = __expf(m1 - nm1);
        m0 = nm0; m1 = nm1;

        float r0 = 0.0f, r1 = 0.0f;
#pragma unroll
        for (int n = 0; n < 8; n++) {
            float e00 = __expf(sc[n][0] - nm0);
            float e01 = __expf(sc[n][1] - nm0);
            float e10 = __expf(sc[n][2] - nm1);
            float e11 = __expf(sc[n][3] - nm1);
            r0 += e00 + e01;
            r1 += e10 + e11;
            uint2 p0; p0.x = f2tf(e00); p0.y = f2tf(e01);
            uint2 p1; p1.x = f2tf(e10); p1.y = f2tf(e11);
            *(uint2*)&sP[g * APITCH + n * 8 + 2 * tig]       = p0;
            *(uint2*)&sP[(g + 8) * APITCH + n * 8 + 2 * tig] = p1;
        }
        r0 += __shfl_xor_sync(0xffffffffu, r0, 1);
        r0 += __shfl_xor_sync(0xffffffffu, r0, 2);
        r1 += __shfl_xor_sync(0xffffffffu, r1, 1);
        r1 += __shfl_xor_sync(0xffffffffu, r1, 2);
        l0 = l0 * cr0 + r0;
        l1 = l1 * cr1 + r1;
#pragma unroll
        for (int dn = 0; dn < 8; dn++) {
            oc[dn][0] *= cr0; oc[dn][1] *= cr0;
            oc[dn][2] *= cr1; oc[dn][3] *= cr1;
        }
        __syncwarp();

        // ---- O += P V ----
#pragma unroll
        for (int kk = 0; kk < 8; kk++) {
            unsigned pa[4];
            pa[0] = sP[g * APITCH + kk * 8 + tig];
            pa[1] = sP[(g + 8) * APITCH + kk * 8 + tig];
            pa[2] = sP[g * APITCH + kk * 8 + tig + 4];
            pa[3] = sP[(g + 8) * APITCH + kk * 8 + tig + 4];
#pragma unroll
            for (int dn = 0; dn < 8; dn++) {
                unsigned b0 = sV[(dn * 8 + g) * APITCH + kk * 8 + tig];
                unsigned b1 = sV[(dn * 8 + g) * APITCH + kk * 8 + tig + 4];
                mma_tf32(oc[dn], pa, b0, b1);
            }
        }
    }

    // ---- epilogue: normalize, write g_O [b*n][h*64+d] ----
    const int b = bh >> 3;
    const int h = bh & 7;
    const float inv0 = 1.0f / l0;
    const float inv1 = 1.0f / l1;
    const int row0 = q0 + w * 16 + g;
    const int row1 = row0 + 8;
    float* O0 = &g_O[((size_t)(b * NSEQ + row0)) * DIMX + h * DHEAD];
    float* O1 = &g_O[((size_t)(b * NSEQ + row1)) * DIMX + h * DHEAD];
#pragma unroll
    for (int dn = 0; dn < 8; dn++) {
        int c = dn * 8 + 2 * tig;
        float2 v0; v0.x = oc[dn][0] * inv0; v0.y = oc[dn][1] * inv0;
        float2 v1; v1.x = oc[dn][2] * inv1; v1.y = oc[dn][3] * inv1;
        *(float2*)&O0[c] = v0;
        *(float2*)&O1[c] = v1;
    }
}

// ---------------------------------------------------------------------------
extern "C" void kernel_launch(void* const* d_in, const int* in_sizes, int n_in,
                              void* d_out, int out_size)
{
    const float* x     = (const float*)d_in[0];  // [4,2048,512]
    const float* w_qkv = (const float*)d_in[1];  // [512,1536]
    const float* w_out = (const float*)d_in[2];  // [512,512]
    const float* b_out = (const float*)d_in[3];  // [512]
    float* out = (float*)d_out;

    cudaFuncSetAttribute(attn_tc_kernel,
                         cudaFuncAttributeMaxDynamicSharedMemorySize,
                         ATT_SMEM_BYTES);

    qkv_gemm_tf32_kernel<<<dim3(N_QKV / 128, M_ROWS / 128), 256>>>(x, w_qkv);
    attn_tc_kernel<<<dim3(NSEQ / 64, BATCH * HEADS), 128, ATT_SMEM_BYTES>>>();
    out_gemm_tf32_kernel<<<dim3(DIMX / 128, M_ROWS / 128), 256>>>(w_out, b_out, out);
}